// round 5
// baseline (speedup 1.0000x reference)
#include <cuda_runtime.h>

#define C 32
#define BMAX 16
#define EPS 1e-5f

// Scratch (device globals: no allocation allowed in kernel_launch)
__device__ float g_sum[BMAX * C];
__device__ float g_sq[BMAX * C];
__device__ float g_cnt[BMAX];
__device__ float g_scale[BMAX * C];
__device__ float g_shift[BMAX * C];

// ---------------------------------------------------------------------------
// Kernel 0: zero the accumulators (must run every graph replay)
// ---------------------------------------------------------------------------
__global__ void zero_stats_kernel() {
    int i = threadIdx.x;
    if (i < BMAX * C) { g_sum[i] = 0.0f; g_sq[i] = 0.0f; }
    if (i < BMAX) g_cnt[i] = 0.0f;
}

// ---------------------------------------------------------------------------
// Kernel 1: per-segment sum / sumsq / count.
// One warp owns a contiguous chunk of rows; lane j owns channel j.
// batch_id is sorted, so if first==last batch in the chunk we take a tight
// loop with no per-row batch_id loads and a single flush.
// ---------------------------------------------------------------------------
__global__ void reduce_kernel(const float* __restrict__ data,
                              const int* __restrict__ bid,
                              int N, int rows_per_warp) {
    int warp = (int)((blockIdx.x * blockDim.x + threadIdx.x) >> 5);
    int lane = threadIdx.x & 31;

    int r0 = warp * rows_per_warp;
    if (r0 >= N) return;
    int r1 = r0 + rows_per_warp;
    if (r1 > N) r1 = N;

    int b_first = bid[r0];
    int b_last = bid[r1 - 1];

    float s = 0.0f, q = 0.0f;

    if (b_first == b_last) {
        // Fast path: single segment — pure streaming.
        const float* p = data + (size_t)r0 * C + lane;
        int rows = r1 - r0;
        int r = 0;
        #pragma unroll 4
        for (; r + 4 <= rows; r += 4) {
            float x0 = p[(size_t)(r + 0) * C];
            float x1 = p[(size_t)(r + 1) * C];
            float x2 = p[(size_t)(r + 2) * C];
            float x3 = p[(size_t)(r + 3) * C];
            s += x0 + x1 + x2 + x3;
            q += x0 * x0 + x1 * x1 + x2 * x2 + x3 * x3;
        }
        for (; r < rows; ++r) {
            float x = p[(size_t)r * C];
            s += x; q += x * x;
        }
        atomicAdd(&g_sum[b_first * C + lane], s);
        atomicAdd(&g_sq[b_first * C + lane], q);
        if (lane == 0) atomicAdd(&g_cnt[b_first], (float)rows);
    } else {
        // Slow path: chunk crosses a segment boundary (<= 15 warps total).
        int cur = b_first;
        float cnt = 0.0f;
        for (int r = r0; r < r1; ++r) {
            int b = bid[r];
            if (b != cur) {
                atomicAdd(&g_sum[cur * C + lane], s);
                atomicAdd(&g_sq[cur * C + lane], q);
                if (lane == 0) atomicAdd(&g_cnt[cur], cnt);
                s = 0.0f; q = 0.0f; cnt = 0.0f; cur = b;
            }
            float x = data[(size_t)r * C + lane];
            s += x; q += x * x; cnt += 1.0f;
        }
        atomicAdd(&g_sum[cur * C + lane], s);
        atomicAdd(&g_sq[cur * C + lane], q);
        if (lane == 0) atomicAdd(&g_cnt[cur], cnt);
    }
}

// ---------------------------------------------------------------------------
// Kernel 2: fold stats into per-(b,c) scale/shift.
// out = (x - mean) * inv_std * w + bias  ==  x*scale + shift
// ---------------------------------------------------------------------------
__global__ void finalize_kernel(const float* __restrict__ w,
                                const float* __restrict__ bias) {
    int i = threadIdx.x;           // 0..BMAX*C-1
    if (i >= BMAX * C) return;
    int b = i / C, c = i % C;
    float cnt = g_cnt[b];
    float norm = 1.0f / (cnt + EPS);
    float sum = g_sum[i];
    float mean = sum * norm;
    float var = (g_sq[i] - 2.0f * mean * sum + mean * mean * cnt) * norm;
    float inv_std = rsqrtf(var + EPS);
    float wc = w ? w[c] : 1.0f;
    float bc = bias ? bias[c] : 0.0f;
    float sc = inv_std * wc;
    g_scale[i] = sc;
    g_shift[i] = bc - mean * sc;
}

// ---------------------------------------------------------------------------
// Kernel 3: normalize.  float4 streaming; 8 float4 per row.
// ---------------------------------------------------------------------------
__global__ void normalize_kernel(const float4* __restrict__ data4,
                                 const int* __restrict__ bid,
                                 float4* __restrict__ out4, int n4) {
    __shared__ float4 s_scale[BMAX * C / 4];
    __shared__ float4 s_shift[BMAX * C / 4];
    for (int i = threadIdx.x; i < BMAX * C / 4; i += blockDim.x) {
        s_scale[i] = reinterpret_cast<const float4*>(g_scale)[i];
        s_shift[i] = reinterpret_cast<const float4*>(g_shift)[i];
    }
    __syncthreads();

    int i = blockIdx.x * blockDim.x + threadIdx.x;
    if (i >= n4) return;
    int row = i >> 3;              // 8 float4 per 32-channel row
    int b = bid[row];
    int q = (b << 3) | (i & 7);    // index into [B][8] float4 table
    float4 d = data4[i];
    float4 sc = s_scale[q];
    float4 sh = s_shift[q];
    float4 o;
    o.x = fmaf(d.x, sc.x, sh.x);
    o.y = fmaf(d.y, sc.y, sh.y);
    o.z = fmaf(d.z, sc.z, sh.z);
    o.w = fmaf(d.w, sc.w, sh.w);
    out4[i] = o;
}

// ---------------------------------------------------------------------------
extern "C" void kernel_launch(void* const* d_in, const int* in_sizes, int n_in,
                              void* d_out, int out_size) {
    const float* data = (const float*)d_in[0];
    const int* bid = (const int*)d_in[1];
    int N = in_sizes[0] / C;

    // Locate weights/bias among the remaining inputs (size-32 fp32 arrays,
    // in order); a size-1 input is batch_size (fixed at 16, unused on host).
    const float* w = nullptr;
    const float* bias = nullptr;
    for (int i = 2; i < n_in; ++i) {
        if (in_sizes[i] == C) {
            if (!w) w = (const float*)d_in[i];
            else if (!bias) bias = (const float*)d_in[i];
        }
    }

    zero_stats_kernel<<<1, BMAX * C>>>();

    const int threads = 256;
    const int blocks = 148 * 8;                 // 9472 warps
    int warps = blocks * (threads / 32);
    int rpw = (N + warps - 1) / warps;
    reduce_kernel<<<blocks, threads>>>(data, bid, N, rpw);

    finalize_kernel<<<1, BMAX * C>>>(w, bias);

    int n4 = N * (C / 4);
    int nblocks = (n4 + threads - 1) / threads;
    normalize_kernel<<<nblocks, threads>>>((const float4*)data, bid,
                                           (float4*)d_out, n4);
}

// round 6
// speedup vs baseline: 1.0622x; 1.0622x over previous
#include <cuda_runtime.h>

#define C 32
#define BMAX 16
#define EPS 1e-5f

// Scratch (device globals: no allocation allowed in kernel_launch)
__device__ float g_sum[BMAX * C];
__device__ float g_sq[BMAX * C];
__device__ float g_cnt[BMAX];
__device__ float g_scale[BMAX * C];
__device__ float g_shift[BMAX * C];

// ---------------------------------------------------------------------------
// Kernel 0: zero the accumulators (must run every graph replay)
// ---------------------------------------------------------------------------
__global__ void zero_stats_kernel() {
    int i = threadIdx.x;
    if (i < BMAX * C) { g_sum[i] = 0.0f; g_sq[i] = 0.0f; }
    if (i < BMAX) g_cnt[i] = 0.0f;
}

// ---------------------------------------------------------------------------
// Kernel 1: per-segment sum / sumsq / count.
// One warp owns a contiguous chunk of rows. batch_id is sorted, so if
// first==last batch in the chunk we take a float4 streaming fast path:
// lane L loads the float4 at column (L&7), row offset (L>>3) -> a warp
// consumes 4 rows per LDG.128 round, unrolled x2 (8 rows, 2 loads in
// flight, independent accumulator chains).
// ---------------------------------------------------------------------------
__global__ void reduce_kernel(const float* __restrict__ data,
                              const int* __restrict__ bid,
                              int N, int rows_per_warp) {
    int warp = (int)((blockIdx.x * blockDim.x + threadIdx.x) >> 5);
    int lane = threadIdx.x & 31;

    int r0 = warp * rows_per_warp;
    if (r0 >= N) return;
    int r1 = r0 + rows_per_warp;
    if (r1 > N) r1 = N;

    int b_first = bid[r0];
    int b_last = bid[r1 - 1];

    if (b_first == b_last) {
        // ---- Fast path: single segment, float4 streaming ----
        const float4* p4 = reinterpret_cast<const float4*>(
            data + (size_t)r0 * C);
        int rows = r1 - r0;
        int sub = lane & 7;        // which float4 column (channels sub*4..+3)
        int rg  = lane >> 3;       // row offset within 4-row group

        float4 s0 = make_float4(0.f, 0.f, 0.f, 0.f);
        float4 q0 = make_float4(0.f, 0.f, 0.f, 0.f);
        float4 s1 = make_float4(0.f, 0.f, 0.f, 0.f);
        float4 q1 = make_float4(0.f, 0.f, 0.f, 0.f);

        int r = 0;
        for (; r + 8 <= rows; r += 8) {
            float4 a = p4[(size_t)(r + rg) * 8 + sub];
            float4 b = p4[(size_t)(r + 4 + rg) * 8 + sub];
            s0.x += a.x; s0.y += a.y; s0.z += a.z; s0.w += a.w;
            q0.x = fmaf(a.x, a.x, q0.x); q0.y = fmaf(a.y, a.y, q0.y);
            q0.z = fmaf(a.z, a.z, q0.z); q0.w = fmaf(a.w, a.w, q0.w);
            s1.x += b.x; s1.y += b.y; s1.z += b.z; s1.w += b.w;
            q1.x = fmaf(b.x, b.x, q1.x); q1.y = fmaf(b.y, b.y, q1.y);
            q1.z = fmaf(b.z, b.z, q1.z); q1.w = fmaf(b.w, b.w, q1.w);
        }
        if (r + 4 <= rows) {
            float4 a = p4[(size_t)(r + rg) * 8 + sub];
            s0.x += a.x; s0.y += a.y; s0.z += a.z; s0.w += a.w;
            q0.x = fmaf(a.x, a.x, q0.x); q0.y = fmaf(a.y, a.y, q0.y);
            q0.z = fmaf(a.z, a.z, q0.z); q0.w = fmaf(a.w, a.w, q0.w);
            r += 4;
        }
        if (r < rows && r + rg < rows) {   // 1-3 remaining rows, predicated
            float4 a = p4[(size_t)(r + rg) * 8 + sub];
            s0.x += a.x; s0.y += a.y; s0.z += a.z; s0.w += a.w;
            q0.x = fmaf(a.x, a.x, q0.x); q0.y = fmaf(a.y, a.y, q0.y);
            q0.z = fmaf(a.z, a.z, q0.z); q0.w = fmaf(a.w, a.w, q0.w);
        }

        s0.x += s1.x; s0.y += s1.y; s0.z += s1.z; s0.w += s1.w;
        q0.x += q1.x; q0.y += q1.y; q0.z += q1.z; q0.w += q1.w;

        // Combine lanes sharing the same channels (rg = 0..3): xor 16, 8.
        #pragma unroll
        for (int off = 16; off >= 8; off >>= 1) {
            s0.x += __shfl_xor_sync(0xffffffffu, s0.x, off);
            s0.y += __shfl_xor_sync(0xffffffffu, s0.y, off);
            s0.z += __shfl_xor_sync(0xffffffffu, s0.z, off);
            s0.w += __shfl_xor_sync(0xffffffffu, s0.w, off);
            q0.x += __shfl_xor_sync(0xffffffffu, q0.x, off);
            q0.y += __shfl_xor_sync(0xffffffffu, q0.y, off);
            q0.z += __shfl_xor_sync(0xffffffffu, q0.z, off);
            q0.w += __shfl_xor_sync(0xffffffffu, q0.w, off);
        }

        if (rg == 0) {   // lanes 0..7 flush channels sub*4 .. sub*4+3
            int base = b_first * C + sub * 4;
            atomicAdd(&g_sum[base + 0], s0.x);
            atomicAdd(&g_sum[base + 1], s0.y);
            atomicAdd(&g_sum[base + 2], s0.z);
            atomicAdd(&g_sum[base + 3], s0.w);
            atomicAdd(&g_sq[base + 0], q0.x);
            atomicAdd(&g_sq[base + 1], q0.y);
            atomicAdd(&g_sq[base + 2], q0.z);
            atomicAdd(&g_sq[base + 3], q0.w);
        }
        if (lane == 0) atomicAdd(&g_cnt[b_first], (float)rows);
    } else {
        // ---- Slow path: chunk crosses a segment boundary (<=15 warps) ----
        int cur = b_first;
        float s = 0.0f, q = 0.0f, cnt = 0.0f;
        for (int r = r0; r < r1; ++r) {
            int b = bid[r];
            if (b != cur) {
                atomicAdd(&g_sum[cur * C + lane], s);
                atomicAdd(&g_sq[cur * C + lane], q);
                if (lane == 0) atomicAdd(&g_cnt[cur], cnt);
                s = 0.0f; q = 0.0f; cnt = 0.0f; cur = b;
            }
            float x = data[(size_t)r * C + lane];
            s += x; q = fmaf(x, x, q); cnt += 1.0f;
        }
        atomicAdd(&g_sum[cur * C + lane], s);
        atomicAdd(&g_sq[cur * C + lane], q);
        if (lane == 0) atomicAdd(&g_cnt[cur], cnt);
    }
}

// ---------------------------------------------------------------------------
// Kernel 2: fold stats into per-(b,c) scale/shift.
// out = (x - mean) * inv_std * w + bias  ==  x*scale + shift
// ---------------------------------------------------------------------------
__global__ void finalize_kernel(const float* __restrict__ w,
                                const float* __restrict__ bias) {
    int i = threadIdx.x;           // 0..BMAX*C-1
    if (i >= BMAX * C) return;
    int b = i / C, c = i % C;
    float cnt = g_cnt[b];
    float norm = 1.0f / (cnt + EPS);
    float sum = g_sum[i];
    float mean = sum * norm;
    float var = (g_sq[i] - 2.0f * mean * sum + mean * mean * cnt) * norm;
    float inv_std = rsqrtf(var + EPS);
    float wc = w ? w[c] : 1.0f;
    float bc = bias ? bias[c] : 0.0f;
    float sc = inv_std * wc;
    g_scale[i] = sc;
    g_shift[i] = bc - mean * sc;
}

// ---------------------------------------------------------------------------
// Kernel 3: normalize. 4 consecutive float4 per thread (64B). The 4 float4s
// never cross a row boundary (4t mod 8 in {0,4}), so one bid load covers all
// four. Streaming hints keep the 512MB of data/out from thrashing L2.
// ---------------------------------------------------------------------------
__global__ void normalize_kernel(const float4* __restrict__ data4,
                                 const int* __restrict__ bid,
                                 float4* __restrict__ out4, int n4) {
    __shared__ float4 s_scale[BMAX * C / 4];
    __shared__ float4 s_shift[BMAX * C / 4];
    for (int i = threadIdx.x; i < BMAX * C / 4; i += blockDim.x) {
        s_scale[i] = reinterpret_cast<const float4*>(g_scale)[i];
        s_shift[i] = reinterpret_cast<const float4*>(g_shift)[i];
    }
    __syncthreads();

    int t = blockIdx.x * blockDim.x + threadIdx.x;
    int i = t * 4;
    if (i >= n4) return;

    int row = i >> 3;
    int b = bid[row];
    int qb = (b << 3) | (i & 7);   // (i&7) in {0,4}; qb..qb+3 same row

    if (i + 3 < n4) {
        float4 d0 = __ldcs(&data4[i + 0]);
        float4 d1 = __ldcs(&data4[i + 1]);
        float4 d2 = __ldcs(&data4[i + 2]);
        float4 d3 = __ldcs(&data4[i + 3]);
        float4 c0 = s_scale[qb + 0], h0 = s_shift[qb + 0];
        float4 c1 = s_scale[qb + 1], h1 = s_shift[qb + 1];
        float4 c2 = s_scale[qb + 2], h2 = s_shift[qb + 2];
        float4 c3 = s_scale[qb + 3], h3 = s_shift[qb + 3];
        float4 o0, o1, o2, o3;
        o0.x = fmaf(d0.x, c0.x, h0.x); o0.y = fmaf(d0.y, c0.y, h0.y);
        o0.z = fmaf(d0.z, c0.z, h0.z); o0.w = fmaf(d0.w, c0.w, h0.w);
        o1.x = fmaf(d1.x, c1.x, h1.x); o1.y = fmaf(d1.y, c1.y, h1.y);
        o1.z = fmaf(d1.z, c1.z, h1.z); o1.w = fmaf(d1.w, c1.w, h1.w);
        o2.x = fmaf(d2.x, c2.x, h2.x); o2.y = fmaf(d2.y, c2.y, h2.y);
        o2.z = fmaf(d2.z, c2.z, h2.z); o2.w = fmaf(d2.w, c2.w, h2.w);
        o3.x = fmaf(d3.x, c3.x, h3.x); o3.y = fmaf(d3.y, c3.y, h3.y);
        o3.z = fmaf(d3.z, c3.z, h3.z); o3.w = fmaf(d3.w, c3.w, h3.w);
        __stcs(&out4[i + 0], o0);
        __stcs(&out4[i + 1], o1);
        __stcs(&out4[i + 2], o2);
        __stcs(&out4[i + 3], o3);
    } else {
        for (int k = 0; k < 4 && i + k < n4; ++k) {
            float4 d = __ldcs(&data4[i + k]);
            float4 c = s_scale[qb + k], h = s_shift[qb + k];
            float4 o;
            o.x = fmaf(d.x, c.x, h.x); o.y = fmaf(d.y, c.y, h.y);
            o.z = fmaf(d.z, c.z, h.z); o.w = fmaf(d.w, c.w, h.w);
            __stcs(&out4[i + k], o);
        }
    }
}

// ---------------------------------------------------------------------------
extern "C" void kernel_launch(void* const* d_in, const int* in_sizes, int n_in,
                              void* d_out, int out_size) {
    const float* data = (const float*)d_in[0];
    const int* bid = (const int*)d_in[1];
    int N = in_sizes[0] / C;

    // Locate weights/bias among the remaining inputs (size-32 fp32 arrays).
    const float* w = nullptr;
    const float* bias = nullptr;
    for (int i = 2; i < n_in; ++i) {
        if (in_sizes[i] == C) {
            if (!w) w = (const float*)d_in[i];
            else if (!bias) bias = (const float*)d_in[i];
        }
    }

    zero_stats_kernel<<<1, BMAX * C>>>();

    const int threads = 256;
    const int blocks = 148 * 8;                 // 9472 warps
    int warps = blocks * (threads / 32);
    int rpw = (N + warps - 1) / warps;
    reduce_kernel<<<blocks, threads>>>(data, bid, N, rpw);

    finalize_kernel<<<1, BMAX * C>>>(w, bias);

    int n4 = N * (C / 4);
    int nthreads_total = (n4 + 3) / 4;
    int nblocks = (nthreads_total + threads - 1) / threads;
    normalize_kernel<<<nblocks, threads>>>((const float4*)data, bid,
                                           (float4*)d_out, n4);
}